// round 5
// baseline (speedup 1.0000x reference)
#include <cuda_runtime.h>
#include <cstdint>

#define NB    32
#define CIN   64
#define COUT  128
#define HDIM  64
#define WDIM  64
#define EPSV  1e-8f
#define FM_OFF (NB * COUT * HDIM * WDIM)

#define NTILES 32768              // 32 n * 32 ty * 32 tx (2x2 output tiles)

// ---- scratch (static __device__, no allocations) ----
__device__ float g_inv_norm[COUT];
__device__ float g_Wt[16 * 2 * 64 * 128];      // [pos][chalf][ci][co_local dup2] = 1MB
__device__ float g_Xt[16 * 64 * NTILES];       // [pos][ci][tile] = 134MB

// ---- helpers ----
__device__ __forceinline__ unsigned long long dup2(float f) {
    unsigned long long r;
    asm("mov.b64 %0,{%1,%1};" : "=l"(r) : "f"(f));
    return r;
}
__device__ __forceinline__ void ffma2(unsigned long long& d, unsigned long long a,
                                      unsigned long long b) {
    asm("fma.rn.f32x2 %0,%1,%2,%0;" : "+l"(d) : "l"(a), "l"(b));
}
__device__ __forceinline__ void cpa16(uint32_t dst, const void* src) {
    asm volatile("cp.async.ca.shared.global [%0], [%1], 16;" :: "r"(dst), "l"(src));
}
__device__ __forceinline__ void cpa8(uint32_t dst, const void* src) {
    asm volatile("cp.async.ca.shared.global [%0], [%1], 8;" :: "r"(dst), "l"(src));
}
__device__ __forceinline__ void cpcommit() {
    asm volatile("cp.async.commit_group;" ::: "memory");
}
template <int N>
__device__ __forceinline__ void cpwait() {
    asm volatile("cp.async.wait_group %0;" :: "n"(N) : "memory");
}

// output transform rows A^T = {{1,1,1,0},{0,1,-1,-1}}
__device__ const float cA0[4] = {1.f, 1.f, 1.f, 0.f};
__device__ const float cA1[4] = {0.f, 1.f, -1.f, -1.f};

// ---------- prep: per-Cout 1/(||k||^2 + eps) ----------
__global__ void prep_norm(const float* __restrict__ kern) {
    __shared__ float red[512];
    int t = threadIdx.x;
    int co = t & 127;
    int part = t >> 7;
    float s = 0.f;
#pragma unroll 4
    for (int i = part * 144; i < part * 144 + 144; i++) {
        float v = kern[i * COUT + co];
        s += v * v;
    }
    red[t] = s;
    __syncthreads();
    if (t < 128)
        g_inv_norm[co] = 1.f / (red[co] + red[co + 128] + red[co + 256] + red[co + 384] + EPSV);
}

// ---------- prep: weight transform W~ = G g G^T, stored duplicated ----------
// G = [[1,0,0],[.5,.5,.5],[.5,-.5,.5],[0,0,1]]
__global__ void prep_Wt(const float* __restrict__ kern) {
    int id = blockIdx.x * 256 + threadIdx.x;   // 8192
    int co = id & 127;
    int ci = id >> 7;

    float g[3][3];
#pragma unroll
    for (int kh = 0; kh < 3; kh++)
#pragma unroll
        for (int kw = 0; kw < 3; kw++)
            g[kh][kw] = kern[(kh * 3 + kw) * (CIN * COUT) + ci * COUT + co];

    float t[4][3];
#pragma unroll
    for (int kw = 0; kw < 3; kw++) {
        t[0][kw] = g[0][kw];
        t[1][kw] = 0.5f * (g[0][kw] + g[1][kw] + g[2][kw]);
        t[2][kw] = 0.5f * (g[0][kw] - g[1][kw] + g[2][kw]);
        t[3][kw] = g[2][kw];
    }
    const int chalf = co >> 6;
    const int col = co & 63;
#pragma unroll
    for (int i = 0; i < 4; i++) {
        float w0 = t[i][0];
        float w1 = 0.5f * (t[i][0] + t[i][1] + t[i][2]);
        float w2 = 0.5f * (t[i][0] - t[i][1] + t[i][2]);
        float w3 = t[i][2];
        float wv[4] = {w0, w1, w2, w3};
#pragma unroll
        for (int j = 0; j < 4; j++) {
            int p = i * 4 + j;
            float2* dst = (float2*)(g_Wt + (((p * 2 + chalf) * 64 + ci) * 128 + col * 2));
            *dst = make_float2(wv[j], wv[j]);
        }
    }
}

// ---------- prep: input transform X~ = B^T d B ----------
// B^T = [[1,0,-1,0],[0,1,1,0],[0,-1,1,0],[0,1,0,-1]]
__global__ __launch_bounds__(256)
void prep_Xt(const float* __restrict__ x) {
    const int bid = blockIdx.x;            // 1024 = n*32 + ty
    const int n = bid >> 5;
    const int ty = bid & 31;
    const int lane = threadIdx.x & 31;
    const int wrp = threadIdx.x >> 5;
    const int tx = lane;
    const int hbase = 2 * ty - 1;
    const int wbase = 2 * tx - 1;
    const int tile = n * 1024 + ty * 32 + tx;

#pragma unroll 1
    for (int it = 0; it < 8; it++) {
        const int ci = wrp * 8 + it;
        const float* xp = x + (n * CIN + ci) * (HDIM * WDIM);

        float d[4][4];
#pragma unroll
        for (int r = 0; r < 4; r++) {
            int gr = hbase + r;
            bool rok = (gr >= 0) & (gr < HDIM);
#pragma unroll
            for (int c = 0; c < 4; c++) {
                int gc = wbase + c;
                bool ok = rok & (gc >= 0) & (gc < WDIM);
                d[r][c] = ok ? xp[gr * WDIM + gc] : 0.f;
            }
        }
        float s[4][4];
#pragma unroll
        for (int c = 0; c < 4; c++) {
            s[0][c] = d[0][c] - d[2][c];
            s[1][c] = d[1][c] + d[2][c];
            s[2][c] = d[2][c] - d[1][c];
            s[3][c] = d[1][c] - d[3][c];
        }
#pragma unroll
        for (int i = 0; i < 4; i++) {
            float v0 = s[i][0] - s[i][2];
            float v1 = s[i][1] + s[i][2];
            float v2 = s[i][2] - s[i][1];
            float v3 = s[i][1] - s[i][3];
            float vv[4] = {v0, v1, v2, v3};
#pragma unroll
            for (int j = 0; j < 4; j++)
                g_Xt[((i * 4 + j) * 64 + ci) * NTILES + tile] = vv[j];
        }
    }
}

// ---------- main: Winograd GEMM (16 pos) + fold + fused LIF/spike ----------
// smem floats: Ws 2x8192 [0,16384), Xs 2x4224 [16384,24832), norm [24832,24896),
//              bias [24896,24960)
#define WS_OFF 0
#define XS_OFF 16384
#define NORM_OFF 24832
#define B_OFF 24896
#define SMEM_FLOATS 24960
#define SMEM_BYTES (SMEM_FLOATS * 4)
#define XROW 132   // padded row stride (floats) per tile-pair

__global__ __launch_bounds__(256, 2)
void wino_gemm(const float* __restrict__ mem, const float* __restrict__ beta_p,
               const float* __restrict__ b_p, float* __restrict__ out) {
    extern __shared__ float sm[];
    const uint32_t smu = (uint32_t)__cvta_generic_to_shared(sm);

    const int tid = threadIdx.x;
    const int cg = tid >> 5;          // co-group 0..7 (warp-uniform)
    const int t2 = tid & 31;          // tile-pair 0..31
    const int bid = blockIdx.x;
    const int chalf = bid & 1;
    const int TB = (bid >> 1) * 64;   // base tile

    if (tid < 64) {
        sm[NORM_OFF + tid] = g_inv_norm[chalf * 64 + tid];
        sm[B_OFF + tid] = b_p[chalf * 64 + tid];
    }

    // stage pos p into buffer buf: W 8192 floats (cp16), X 64ci x 64tile (cp8)
#define STAGE(p, buf)                                                           \
    {                                                                           \
        const float4* wsrc = (const float4*)(g_Wt + (((p)*2 + chalf) << 13));   \
        uint32_t wdst = smu + (WS_OFF + (buf)*8192) * 4;                        \
        _Pragma("unroll")                                                       \
        for (int i = 0; i < 8; i++)                                             \
            cpa16(wdst + (tid + i * 256) * 16, wsrc + tid + i * 256);           \
        const float* xsrc = g_Xt + ((p)*64) * NTILES + TB;                      \
        uint32_t xdst = smu + (XS_OFF + (buf)*4224) * 4;                        \
        _Pragma("unroll")                                                       \
        for (int i = 0; i < 8; i++) {                                           \
            int q = tid + i * 256;                                              \
            int ciq = q >> 5;                                                   \
            int aq = q & 31;                                                    \
            cpa8(xdst + (aq * XROW + ciq * 2) * 4, xsrc + ciq * NTILES + 2 * aq); \
        }                                                                       \
    }

    unsigned long long acc[8][4];     // [co][py*2+px], lanes = (tile even, tile odd)
#pragma unroll
    for (int c = 0; c < 8; c++)
#pragma unroll
        for (int q = 0; q < 4; q++) acc[c][q] = 0ull;

    STAGE(0, 0);
    cpcommit();

#pragma unroll 1
    for (int p = 0; p < 16; p++) {
        const int buf = p & 1;
        cpwait<0>();
        __syncthreads();
        if (p < 15) {
            STAGE(p + 1, buf ^ 1);
            cpcommit();
        }

        const float* Xp = sm + XS_OFF + buf * 4224 + t2 * XROW;
        const float* Wp = sm + WS_OFF + buf * 8192 + cg * 16;

        unsigned long long m[8];
#pragma unroll
        for (int c = 0; c < 8; c++) m[c] = 0ull;

#pragma unroll 2
        for (int ci2 = 0; ci2 < 32; ci2++) {
            ulonglong2 xv = *(const ulonglong2*)(Xp + ci2 * 4);  // ci, ci+1 tile-pairs
            const ulonglong2* w0 = (const ulonglong2*)(Wp + (2 * ci2) * 128);
            ulonglong2 wa = w0[0], wb = w0[1], wc = w0[2], wd = w0[3];
            ffma2(m[0], xv.x, wa.x); ffma2(m[1], xv.x, wa.y);
            ffma2(m[2], xv.x, wb.x); ffma2(m[3], xv.x, wb.y);
            ffma2(m[4], xv.x, wc.x); ffma2(m[5], xv.x, wc.y);
            ffma2(m[6], xv.x, wd.x); ffma2(m[7], xv.x, wd.y);
            const ulonglong2* w1 = (const ulonglong2*)(Wp + (2 * ci2 + 1) * 128);
            wa = w1[0]; wb = w1[1]; wc = w1[2]; wd = w1[3];
            ffma2(m[0], xv.y, wa.x); ffma2(m[1], xv.y, wa.y);
            ffma2(m[2], xv.y, wb.x); ffma2(m[3], xv.y, wb.y);
            ffma2(m[4], xv.y, wc.x); ffma2(m[5], xv.y, wc.y);
            ffma2(m[6], xv.y, wd.x); ffma2(m[7], xv.y, wd.y);
        }

        // fold: acc[py][px] += AT[py][i]*AT[px][j] * m
        const int fi = p >> 2, fj = p & 3;
        const float a0i = cA0[fi], a1i = cA1[fi];
        const float a0j = cA0[fj], a1j = cA1[fj];
        unsigned long long d00 = dup2(a0i * a0j);
        unsigned long long d01 = dup2(a0i * a1j);
        unsigned long long d10 = dup2(a1i * a0j);
        unsigned long long d11 = dup2(a1i * a1j);
#pragma unroll
        for (int c = 0; c < 8; c++) {
            ffma2(acc[c][0], d00, m[c]);
            ffma2(acc[c][1], d01, m[c]);
            ffma2(acc[c][2], d10, m[c]);
            ffma2(acc[c][3], d11, m[c]);
        }
    }

    // ---- fused epilogue: LIF membrane + multi-threshold spike ----
    const int g0 = TB + 2 * t2;
    const int n = g0 >> 10;
    const int rem = g0 & 1023;
    const int ty = rem >> 5;
    const int wc0 = (rem & 31) * 2;
    const float beta = *beta_p;
    const float omb = 1.f - beta;

#pragma unroll
    for (int c = 0; c < 8; c++) {
        const int col = cg * 8 + c;
        const int co = chalf * 64 + col;
        const float invn = sm[NORM_OFF + col];
        const float bb = sm[B_OFF + col];
#pragma unroll
        for (int py = 0; py < 2; py++) {
            const int idx = ((n * COUT + co) * HDIM + 2 * ty + py) * WDIM + wc0;
            float4 m4 = *(const float4*)(mem + idx);
            float2 pa = *(float2*)&acc[c][py * 2 + 0];   // px=0: tiles (even, odd)
            float2 pb = *(float2*)&acc[c][py * 2 + 1];   // px=1
            float cv[4] = {pa.x, pb.x, pa.y, pb.y};
            float mv[4] = {m4.x, m4.y, m4.z, m4.w};
            float sv[4], fv[4];
#pragma unroll
            for (int w = 0; w < 4; w++) {
                float nm = mv[w] * beta + cv[w] * omb;
                float mt = nm * invn - bb;
                float cnt = (float)((mt > 0.f) + (mt > 1.f) + (mt > 2.f) + (mt > 3.f));
                sv[w] = cnt;
                fv[w] = (cnt > 0.f) ? 0.f : nm;
            }
            *(float4*)(out + idx) = make_float4(sv[0], sv[1], sv[2], sv[3]);
            *(float4*)(out + FM_OFF + idx) = make_float4(fv[0], fv[1], fv[2], fv[3]);
        }
    }
}

extern "C" void kernel_launch(void* const* d_in, const int* in_sizes, int n_in,
                              void* d_out, int out_size) {
    const float* x    = (const float*)d_in[0];
    const float* mem  = (const float*)d_in[1];
    const float* kern = (const float*)d_in[2];
    const float* beta = (const float*)d_in[3];
    const float* b    = (const float*)d_in[4];
    float* out = (float*)d_out;

    cudaFuncSetAttribute(wino_gemm, cudaFuncAttributeMaxDynamicSharedMemorySize,
                         SMEM_BYTES);

    prep_norm<<<1, 512>>>(kern);
    prep_Wt<<<32, 256>>>(kern);
    prep_Xt<<<1024, 256>>>(x);
    wino_gemm<<<1024, 256, SMEM_BYTES>>>(mem, beta, b, out);
}

// round 6
// speedup vs baseline: 1.3643x; 1.3643x over previous
#include <cuda_runtime.h>
#include <cstdint>

#define NB    32
#define CIN   64
#define COUT  128
#define HDIM  64
#define WDIM  64
#define EPSV  1e-8f
#define FM_OFF (NB * COUT * HDIM * WDIM)

#define NTILES 32768              // 32 n * 32 ty * 32 tx (2x2 output tiles)

// ---- scratch (static __device__, no allocations) ----
__device__ float g_inv_norm[COUT];
__device__ float g_Wt[16 * 2 * 64 * 64];       // [pos][chalf][ci][co_local] 512KB
__device__ float g_Xt[16 * 64 * NTILES];       // [pos][ci][tile] = 134MB

// ---- helpers ----
__device__ __forceinline__ unsigned long long dup2(float f) {
    unsigned long long r;
    asm("mov.b64 %0,{%1,%1};" : "=l"(r) : "f"(f));
    return r;
}
__device__ __forceinline__ void ffma2(unsigned long long& d, unsigned long long a,
                                      unsigned long long b) {
    asm("fma.rn.f32x2 %0,%1,%2,%0;" : "+l"(d) : "l"(a), "l"(b));
}
__device__ __forceinline__ void cpa16(uint32_t dst, const void* src) {
    asm volatile("cp.async.ca.shared.global [%0], [%1], 16;" :: "r"(dst), "l"(src));
}
__device__ __forceinline__ void cpcommit() {
    asm volatile("cp.async.commit_group;" ::: "memory");
}
template <int N>
__device__ __forceinline__ void cpwait() {
    asm volatile("cp.async.wait_group %0;" :: "n"(N) : "memory");
}

// output transform rows A^T = {{1,1,1,0},{0,1,-1,-1}}
__device__ const float cA0[4] = {1.f, 1.f, 1.f, 0.f};
__device__ const float cA1[4] = {0.f, 1.f, -1.f, -1.f};

// ---------- prep: per-Cout 1/(||k||^2 + eps) ----------
__global__ void prep_norm(const float* __restrict__ kern) {
    __shared__ float red[512];
    int t = threadIdx.x;
    int co = t & 127;
    int part = t >> 7;
    float s = 0.f;
#pragma unroll 4
    for (int i = part * 144; i < part * 144 + 144; i++) {
        float v = kern[i * COUT + co];
        s += v * v;
    }
    red[t] = s;
    __syncthreads();
    if (t < 128)
        g_inv_norm[co] = 1.f / (red[co] + red[co + 128] + red[co + 256] + red[co + 384] + EPSV);
}

// ---------- prep: weight transform W~ = G g G^T ----------
// G = [[1,0,0],[.5,.5,.5],[.5,-.5,.5],[0,0,1]]
__global__ void prep_Wt(const float* __restrict__ kern) {
    int id = blockIdx.x * 256 + threadIdx.x;   // 8192
    int co = id & 127;
    int ci = id >> 7;

    float g[3][3];
#pragma unroll
    for (int kh = 0; kh < 3; kh++)
#pragma unroll
        for (int kw = 0; kw < 3; kw++)
            g[kh][kw] = kern[(kh * 3 + kw) * (CIN * COUT) + ci * COUT + co];

    float t[4][3];
#pragma unroll
    for (int kw = 0; kw < 3; kw++) {
        t[0][kw] = g[0][kw];
        t[1][kw] = 0.5f * (g[0][kw] + g[1][kw] + g[2][kw]);
        t[2][kw] = 0.5f * (g[0][kw] - g[1][kw] + g[2][kw]);
        t[3][kw] = g[2][kw];
    }
    const int chalf = co >> 6;
    const int col = co & 63;
#pragma unroll
    for (int i = 0; i < 4; i++) {
        float w0 = t[i][0];
        float w1 = 0.5f * (t[i][0] + t[i][1] + t[i][2]);
        float w2 = 0.5f * (t[i][0] - t[i][1] + t[i][2]);
        float w3 = t[i][2];
        float wv[4] = {w0, w1, w2, w3};
#pragma unroll
        for (int j = 0; j < 4; j++) {
            int p = i * 4 + j;
            g_Wt[((p * 2 + chalf) * 64 + ci) * 64 + col] = wv[j];
        }
    }
}

// ---------- prep: input transform X~ = B^T d B ----------
// B^T = [[1,0,-1,0],[0,1,1,0],[0,-1,1,0],[0,1,0,-1]]
__global__ __launch_bounds__(256)
void prep_Xt(const float* __restrict__ x) {
    const int bid = blockIdx.x;            // 1024 = n*32 + ty
    const int n = bid >> 5;
    const int ty = bid & 31;
    const int lane = threadIdx.x & 31;
    const int wrp = threadIdx.x >> 5;
    const int tx = lane;
    const int hbase = 2 * ty - 1;
    const int wbase = 2 * tx - 1;
    const int tile = n * 1024 + ty * 32 + tx;

#pragma unroll 1
    for (int it = 0; it < 8; it++) {
        const int ci = wrp * 8 + it;
        const float* xp = x + (n * CIN + ci) * (HDIM * WDIM);

        float d[4][4];
#pragma unroll
        for (int r = 0; r < 4; r++) {
            int gr = hbase + r;
            bool rok = (gr >= 0) & (gr < HDIM);
#pragma unroll
            for (int c = 0; c < 4; c++) {
                int gc = wbase + c;
                bool ok = rok & (gc >= 0) & (gc < WDIM);
                d[r][c] = ok ? xp[gr * WDIM + gc] : 0.f;
            }
        }
        float s[4][4];
#pragma unroll
        for (int c = 0; c < 4; c++) {
            s[0][c] = d[0][c] - d[2][c];
            s[1][c] = d[1][c] + d[2][c];
            s[2][c] = d[2][c] - d[1][c];
            s[3][c] = d[1][c] - d[3][c];
        }
#pragma unroll
        for (int i = 0; i < 4; i++) {
            float v0 = s[i][0] - s[i][2];
            float v1 = s[i][1] + s[i][2];
            float v2 = s[i][2] - s[i][1];
            float v3 = s[i][1] - s[i][3];
            float vv[4] = {v0, v1, v2, v3};
#pragma unroll
            for (int j = 0; j < 4; j++)
                g_Xt[((i * 4 + j) * 64 + ci) * NTILES + tile] = vv[j];
        }
    }
}

// ---------- main: Winograd GEMM (16 pos) + fold + fused LIF/spike ----------
// smem floats: Ws 2x4096 [0,8192)  [ci][co 64]
//              Xs 2x4096 [8192,16384)  [ci][tile 64]
//              norm [16384,16448)  bias [16448,16512)
#define WS_OFF 0
#define XS_OFF 8192
#define NORM_OFF 16384
#define B_OFF 16448
#define SMEM_FLOATS 16512
#define SMEM_BYTES (SMEM_FLOATS * 4)

__global__ __launch_bounds__(256, 2)
void wino_gemm(const float* __restrict__ mem, const float* __restrict__ beta_p,
               const float* __restrict__ b_p, float* __restrict__ out) {
    extern __shared__ float sm[];
    const uint32_t smu = (uint32_t)__cvta_generic_to_shared(sm);

    const int tid = threadIdx.x;
    const int lane = tid & 31;
    const int wrp = tid >> 5;
    const int q4 = wrp & 3;           // co quarter (16 co)
    const int th = wrp >> 2;          // tile half (32 tiles)
    const int cog = lane & 7;         // co pair within quarter
    const int tg = lane >> 3;         // tile octet within half
    const int bid = blockIdx.x;
    const int chalf = bid & 1;
    const int TB = (bid >> 1) * 64;   // base tile

    if (tid < 64) {
        sm[NORM_OFF + tid] = g_inv_norm[chalf * 64 + tid];
        sm[B_OFF + tid] = b_p[chalf * 64 + tid];
    }

    // stage pos p into buffer buf: W [ci][co] 16KB, X [ci][tile] 16KB
#define STAGE(p, buf)                                                           \
    {                                                                           \
        const float4* wsrc = (const float4*)(g_Wt + (((p)*2 + chalf) << 12));   \
        uint32_t wdst = smu + (WS_OFF + (buf)*4096) * 4;                        \
        _Pragma("unroll")                                                       \
        for (int i = 0; i < 4; i++)                                             \
            cpa16(wdst + (tid + i * 256) * 16, wsrc + tid + i * 256);           \
        const float* xsrc = g_Xt + ((p)*64) * NTILES + TB;                      \
        uint32_t xdst = smu + (XS_OFF + (buf)*4096) * 4;                        \
        _Pragma("unroll")                                                       \
        for (int i = 0; i < 4; i++) {                                           \
            int q = tid + i * 256;                                              \
            int ciq = q >> 4;                                                   \
            int t4 = q & 15;                                                    \
            cpa16(xdst + q * 16, xsrc + ciq * NTILES + t4 * 4);                 \
        }                                                                       \
    }

    // acc[c][tp][q]: c = co within pair, tp = tile pair, q = py*2+px
    unsigned long long acc[2][4][4];
#pragma unroll
    for (int c = 0; c < 2; c++)
#pragma unroll
        for (int tp = 0; tp < 4; tp++)
#pragma unroll
            for (int q = 0; q < 4; q++) acc[c][tp][q] = 0ull;

    STAGE(0, 0);
    cpcommit();

#pragma unroll 1
    for (int p = 0; p < 16; p++) {
        const int buf = p & 1;
        cpwait<0>();
        __syncthreads();
        if (p < 15) {
            STAGE(p + 1, buf ^ 1);
            cpcommit();
        }

        const float* Wp = sm + WS_OFF + buf * 4096 + q4 * 16 + cog * 2;
        const float* Xp = sm + XS_OFF + buf * 4096 + th * 32 + tg * 8;

        unsigned long long m[2][4];
#pragma unroll
        for (int c = 0; c < 2; c++)
#pragma unroll
            for (int tp = 0; tp < 4; tp++) m[c][tp] = 0ull;

#pragma unroll 4
        for (int ci = 0; ci < 64; ci++) {
            float2 wv = *(const float2*)(Wp + ci * 64);      // LDS.64, 2 co
            ulonglong2 xa = *(const ulonglong2*)(Xp + ci * 64);      // tiles 0-3
            ulonglong2 xb = *(const ulonglong2*)(Xp + ci * 64 + 4);  // tiles 4-7
            unsigned long long w0 = dup2(wv.x);
            unsigned long long w1 = dup2(wv.y);
            ffma2(m[0][0], w0, xa.x); ffma2(m[0][1], w0, xa.y);
            ffma2(m[0][2], w0, xb.x); ffma2(m[0][3], w0, xb.y);
            ffma2(m[1][0], w1, xa.x); ffma2(m[1][1], w1, xa.y);
            ffma2(m[1][2], w1, xb.x); ffma2(m[1][3], w1, xb.y);
        }

        // fold: acc[q] += AT[py][i]*AT[px][j] * m
        const int fi = p >> 2, fj = p & 3;
        const float a0i = cA0[fi], a1i = cA1[fi];
        const float a0j = cA0[fj], a1j = cA1[fj];
        unsigned long long d00 = dup2(a0i * a0j);
        unsigned long long d01 = dup2(a0i * a1j);
        unsigned long long d10 = dup2(a1i * a0j);
        unsigned long long d11 = dup2(a1i * a1j);
#pragma unroll
        for (int c = 0; c < 2; c++)
#pragma unroll
            for (int tp = 0; tp < 4; tp++) {
                ffma2(acc[c][tp][0], d00, m[c][tp]);
                ffma2(acc[c][tp][1], d01, m[c][tp]);
                ffma2(acc[c][tp][2], d10, m[c][tp]);
                ffma2(acc[c][tp][3], d11, m[c][tp]);
            }
    }

    // ---- fused epilogue: LIF membrane + multi-threshold spike ----
    const float beta = *beta_p;
    const float omb = 1.f - beta;

#pragma unroll
    for (int c = 0; c < 2; c++) {
        const int col = q4 * 16 + cog * 2 + c;
        const int co = chalf * 64 + col;
        const float invn = sm[NORM_OFF + col];
        const float bb = sm[B_OFF + col];
#pragma unroll
        for (int tp = 0; tp < 4; tp++) {
            const int g0 = TB + th * 32 + tg * 8 + tp * 2;   // even tile of pair
            const int n = g0 >> 10;
            const int rem = g0 & 1023;
            const int ty = rem >> 5;
            const int wc0 = (rem & 31) * 2;
#pragma unroll
            for (int py = 0; py < 2; py++) {
                const int idx = ((n * COUT + co) * HDIM + 2 * ty + py) * WDIM + wc0;
                float4 m4 = *(const float4*)(mem + idx);
                float2 p0 = *(float2*)&acc[c][tp][py * 2 + 0];  // px=0 (t even, t odd)
                float2 p1 = *(float2*)&acc[c][tp][py * 2 + 1];  // px=1
                float cv[4] = {p0.x, p1.x, p0.y, p1.y};
                float mv[4] = {m4.x, m4.y, m4.z, m4.w};
                float sv[4], fv[4];
#pragma unroll
                for (int w = 0; w < 4; w++) {
                    float nm = mv[w] * beta + cv[w] * omb;
                    float mt = nm * invn - bb;
                    float cnt =
                        (float)((mt > 0.f) + (mt > 1.f) + (mt > 2.f) + (mt > 3.f));
                    sv[w] = cnt;
                    fv[w] = (cnt > 0.f) ? 0.f : nm;
                }
                *(float4*)(out + idx) = make_float4(sv[0], sv[1], sv[2], sv[3]);
                *(float4*)(out + FM_OFF + idx) =
                    make_float4(fv[0], fv[1], fv[2], fv[3]);
            }
        }
    }
}

extern "C" void kernel_launch(void* const* d_in, const int* in_sizes, int n_in,
                              void* d_out, int out_size) {
    const float* x    = (const float*)d_in[0];
    const float* mem  = (const float*)d_in[1];
    const float* kern = (const float*)d_in[2];
    const float* beta = (const float*)d_in[3];
    const float* b    = (const float*)d_in[4];
    float* out = (float*)d_out;

    cudaFuncSetAttribute(wino_gemm, cudaFuncAttributeMaxDynamicSharedMemorySize,
                         SMEM_BYTES);

    prep_norm<<<1, 512>>>(kern);
    prep_Wt<<<32, 256>>>(kern);
    prep_Xt<<<1024, 256>>>(x);
    wino_gemm<<<1024, 256, SMEM_BYTES>>>(mem, beta, b, out);
}

// round 7
// speedup vs baseline: 1.3659x; 1.0011x over previous
#include <cuda_runtime.h>
#include <cstdint>

#define NB    32
#define CIN   64
#define COUT  128
#define HDIM  64
#define WDIM  64
#define EPSV  1e-8f
#define FM_OFF (NB * COUT * HDIM * WDIM)

#define NTILES 32768              // 32 n * 32 ty * 32 tx (2x2 output tiles)

// ---- scratch (static __device__, no allocations) ----
__device__ float g_inv_norm[COUT];
__device__ float g_Wt[16 * 2 * 64 * 64];       // [pos][chalf][ci][co_local] 512KB
__device__ float g_Xt[16 * 64 * NTILES];       // [pos][ci][tile] = 134MB

// ---- helpers ----
__device__ __forceinline__ unsigned long long dup2(float f) {
    unsigned long long r;
    asm("mov.b64 %0,{%1,%1};" : "=l"(r) : "f"(f));
    return r;
}
__device__ __forceinline__ void ffma2(unsigned long long& d, unsigned long long a,
                                      unsigned long long b) {
    asm("fma.rn.f32x2 %0,%1,%2,%0;" : "+l"(d) : "l"(a), "l"(b));
}
__device__ __forceinline__ void cpa16(uint32_t dst, const void* src) {
    asm volatile("cp.async.ca.shared.global [%0], [%1], 16;" :: "r"(dst), "l"(src));
}
__device__ __forceinline__ void cpcommit() {
    asm volatile("cp.async.commit_group;" ::: "memory");
}
template <int N>
__device__ __forceinline__ void cpwait() {
    asm volatile("cp.async.wait_group %0;" :: "n"(N) : "memory");
}

// output transform rows A^T = {{1,1,1,0},{0,1,-1,-1}}
__device__ const float cA0[4] = {1.f, 1.f, 1.f, 0.f};
__device__ const float cA1[4] = {0.f, 1.f, -1.f, -1.f};

// ---------- prep: per-Cout 1/(||k||^2 + eps) ----------
__global__ void prep_norm(const float* __restrict__ kern) {
    __shared__ float red[512];
    int t = threadIdx.x;
    int co = t & 127;
    int part = t >> 7;
    float s = 0.f;
#pragma unroll 4
    for (int i = part * 144; i < part * 144 + 144; i++) {
        float v = kern[i * COUT + co];
        s += v * v;
    }
    red[t] = s;
    __syncthreads();
    if (t < 128)
        g_inv_norm[co] = 1.f / (red[co] + red[co + 128] + red[co + 256] + red[co + 384] + EPSV);
}

// ---------- prep: weight transform W~ = G g G^T ----------
// G = [[1,0,0],[.5,.5,.5],[.5,-.5,.5],[0,0,1]]
__global__ void prep_Wt(const float* __restrict__ kern) {
    int id = blockIdx.x * 256 + threadIdx.x;   // 8192
    int co = id & 127;
    int ci = id >> 7;

    float g[3][3];
#pragma unroll
    for (int kh = 0; kh < 3; kh++)
#pragma unroll
        for (int kw = 0; kw < 3; kw++)
            g[kh][kw] = kern[(kh * 3 + kw) * (CIN * COUT) + ci * COUT + co];

    float t[4][3];
#pragma unroll
    for (int kw = 0; kw < 3; kw++) {
        t[0][kw] = g[0][kw];
        t[1][kw] = 0.5f * (g[0][kw] + g[1][kw] + g[2][kw]);
        t[2][kw] = 0.5f * (g[0][kw] - g[1][kw] + g[2][kw]);
        t[3][kw] = g[2][kw];
    }
    const int chalf = co >> 6;
    const int col = co & 63;
#pragma unroll
    for (int i = 0; i < 4; i++) {
        float w0 = t[i][0];
        float w1 = 0.5f * (t[i][0] + t[i][1] + t[i][2]);
        float w2 = 0.5f * (t[i][0] - t[i][1] + t[i][2]);
        float w3 = t[i][2];
        float wv[4] = {w0, w1, w2, w3};
#pragma unroll
        for (int j = 0; j < 4; j++) {
            int p = i * 4 + j;
            g_Wt[((p * 2 + chalf) * 64 + ci) * 64 + col] = wv[j];
        }
    }
}

// ---------- prep: input transform X~ = B^T d B ----------
// B^T = [[1,0,-1,0],[0,1,1,0],[0,-1,1,0],[0,1,0,-1]]
__global__ __launch_bounds__(256)
void prep_Xt(const float* __restrict__ x) {
    const int bid = blockIdx.x;            // 1024 = n*32 + ty
    const int n = bid >> 5;
    const int ty = bid & 31;
    const int lane = threadIdx.x & 31;
    const int wrp = threadIdx.x >> 5;
    const int tx = lane;
    const int hbase = 2 * ty - 1;
    const int wbase = 2 * tx - 1;
    const int tile = n * 1024 + ty * 32 + tx;

#pragma unroll 1
    for (int it = 0; it < 8; it++) {
        const int ci = wrp * 8 + it;
        const float* xp = x + (n * CIN + ci) * (HDIM * WDIM);

        float d[4][4];
#pragma unroll
        for (int r = 0; r < 4; r++) {
            int gr = hbase + r;
            bool rok = (gr >= 0) & (gr < HDIM);
#pragma unroll
            for (int c = 0; c < 4; c++) {
                int gc = wbase + c;
                bool ok = rok & (gc >= 0) & (gc < WDIM);
                d[r][c] = ok ? xp[gr * WDIM + gc] : 0.f;
            }
        }
        float s[4][4];
#pragma unroll
        for (int c = 0; c < 4; c++) {
            s[0][c] = d[0][c] - d[2][c];
            s[1][c] = d[1][c] + d[2][c];
            s[2][c] = d[2][c] - d[1][c];
            s[3][c] = d[1][c] - d[3][c];
        }
#pragma unroll
        for (int i = 0; i < 4; i++) {
            float v0 = s[i][0] - s[i][2];
            float v1 = s[i][1] + s[i][2];
            float v2 = s[i][2] - s[i][1];
            float v3 = s[i][1] - s[i][3];
            float vv[4] = {v0, v1, v2, v3};
#pragma unroll
            for (int j = 0; j < 4; j++)
                g_Xt[((i * 4 + j) * 64 + ci) * NTILES + tile] = vv[j];
        }
    }
}

// ---------- main: Winograd GEMM (16 pos) + fold + fused LIF/spike ----------
// smem floats: Ws 2x4096 [0,8192)  [ci][co 64]
//              Xs 2x4096 [8192,16384)  [ci][tile 64]
//              norm [16384,16448)  bias [16448,16512)
#define WS_OFF 0
#define XS_OFF 8192
#define NORM_OFF 16384
#define B_OFF 16448
#define SMEM_FLOATS 16512
#define SMEM_BYTES (SMEM_FLOATS * 4)

__global__ __launch_bounds__(256, 2)
void wino_gemm(const float* __restrict__ mem, const float* __restrict__ beta_p,
               const float* __restrict__ b_p, float* __restrict__ out) {
    extern __shared__ float sm[];
    const uint32_t smu = (uint32_t)__cvta_generic_to_shared(sm);

    const int tid = threadIdx.x;
    const int lane = tid & 31;
    const int wrp = tid >> 5;
    const int ch = wrp & 1;           // co half within CTA's 64 (32 co per warp)
    const int tq = wrp >> 1;          // tile quarter (16 tiles per warp)
    const int cg = lane & 7;          // co group: 4 co per thread
    const int tg = lane >> 3;         // tile group: 4 tiles per thread
    const int bid = blockIdx.x;
    const int chalf = bid & 1;
    const int TB = (bid >> 1) * 64;   // base tile

    if (tid < 64) {
        sm[NORM_OFF + tid] = g_inv_norm[chalf * 64 + tid];
        sm[B_OFF + tid] = b_p[chalf * 64 + tid];
    }

    // stage pos p into buffer buf: W [ci][co] 16KB, X [ci][tile] 16KB
#define STAGE(p, buf)                                                           \
    {                                                                           \
        const float4* wsrc = (const float4*)(g_Wt + (((p)*2 + chalf) << 12));   \
        uint32_t wdst = smu + (WS_OFF + (buf)*4096) * 4;                        \
        _Pragma("unroll")                                                       \
        for (int i = 0; i < 4; i++)                                             \
            cpa16(wdst + (tid + i * 256) * 16, wsrc + tid + i * 256);           \
        const float* xsrc = g_Xt + ((p)*64) * NTILES + TB;                      \
        uint32_t xdst = smu + (XS_OFF + (buf)*4096) * 4;                        \
        _Pragma("unroll")                                                       \
        for (int i = 0; i < 4; i++) {                                           \
            int q = tid + i * 256;                                              \
            int ciq = q >> 4;                                                   \
            int t4 = q & 15;                                                    \
            cpa16(xdst + q * 16, xsrc + ciq * NTILES + t4 * 4);                 \
        }                                                                       \
    }

    // acc[c][tp][q]: c = co (4), tp = tile pair (2), q = py*2+px
    unsigned long long acc[4][2][4];
#pragma unroll
    for (int c = 0; c < 4; c++)
#pragma unroll
        for (int tp = 0; tp < 2; tp++)
#pragma unroll
            for (int q = 0; q < 4; q++) acc[c][tp][q] = 0ull;

    STAGE(0, 0);
    cpcommit();

#pragma unroll 1
    for (int p = 0; p < 16; p++) {
        const int buf = p & 1;
        cpwait<0>();
        __syncthreads();
        if (p < 15) {
            STAGE(p + 1, buf ^ 1);
            cpcommit();
        }

        const float* Wp = sm + WS_OFF + buf * 4096 + ch * 32 + cg * 4;
        const float* Xp = sm + XS_OFF + buf * 4096 + tq * 16 + tg * 4;

        unsigned long long m[4][2];
#pragma unroll
        for (int c = 0; c < 4; c++)
#pragma unroll
            for (int tp = 0; tp < 2; tp++) m[c][tp] = 0ull;

#pragma unroll 4
        for (int ci = 0; ci < 64; ci++) {
            float4 wv = *(const float4*)(Wp + ci * 64);           // 4 co
            ulonglong2 xv = *(const ulonglong2*)(Xp + ci * 64);   // 4 tiles (2 pairs)
            unsigned long long w0 = dup2(wv.x);
            unsigned long long w1 = dup2(wv.y);
            unsigned long long w2 = dup2(wv.z);
            unsigned long long w3 = dup2(wv.w);
            ffma2(m[0][0], w0, xv.x); ffma2(m[0][1], w0, xv.y);
            ffma2(m[1][0], w1, xv.x); ffma2(m[1][1], w1, xv.y);
            ffma2(m[2][0], w2, xv.x); ffma2(m[2][1], w2, xv.y);
            ffma2(m[3][0], w3, xv.x); ffma2(m[3][1], w3, xv.y);
        }

        // fold: acc[q] += AT[py][i]*AT[px][j] * m
        const int fi = p >> 2, fj = p & 3;
        const float a0i = cA0[fi], a1i = cA1[fi];
        const float a0j = cA0[fj], a1j = cA1[fj];
        unsigned long long d00 = dup2(a0i * a0j);
        unsigned long long d01 = dup2(a0i * a1j);
        unsigned long long d10 = dup2(a1i * a0j);
        unsigned long long d11 = dup2(a1i * a1j);
#pragma unroll
        for (int c = 0; c < 4; c++)
#pragma unroll
            for (int tp = 0; tp < 2; tp++) {
                ffma2(acc[c][tp][0], d00, m[c][tp]);
                ffma2(acc[c][tp][1], d01, m[c][tp]);
                ffma2(acc[c][tp][2], d10, m[c][tp]);
                ffma2(acc[c][tp][3], d11, m[c][tp]);
            }
    }

    // ---- fused epilogue: LIF membrane + multi-threshold spike ----
    const float beta = *beta_p;
    const float omb = 1.f - beta;
    const int g0 = TB + tq * 16 + tg * 4;   // first of 4 consecutive tiles
    const int n = g0 >> 10;
    const int rem = g0 & 1023;
    const int ty = rem >> 5;
    const int wc0 = (rem & 31) * 2;          // 8 output columns wc0..wc0+7

#pragma unroll
    for (int c = 0; c < 4; c++) {
        const int col = ch * 32 + cg * 4 + c;
        const int co = chalf * 64 + col;
        const float invn = sm[NORM_OFF + col];
        const float bb = sm[B_OFF + col];
#pragma unroll
        for (int py = 0; py < 2; py++) {
            const int idx = ((n * COUT + co) * HDIM + 2 * ty + py) * WDIM + wc0;
            float4 m4a = *(const float4*)(mem + idx);
            float4 m4b = *(const float4*)(mem + idx + 4);
            // tp=0: tiles (t0,t1) -> w 0..3 ; tp=1: tiles (t2,t3) -> w 4..7
            float2 p00 = *(float2*)&acc[c][0][py * 2 + 0];  // (w0, w2)
            float2 p01 = *(float2*)&acc[c][0][py * 2 + 1];  // (w1, w3)
            float2 p10 = *(float2*)&acc[c][1][py * 2 + 0];  // (w4, w6)
            float2 p11 = *(float2*)&acc[c][1][py * 2 + 1];  // (w5, w7)
            float cv[8] = {p00.x, p01.x, p00.y, p01.y, p10.x, p11.x, p10.y, p11.y};
            float mv[8] = {m4a.x, m4a.y, m4a.z, m4a.w, m4b.x, m4b.y, m4b.z, m4b.w};
            float sv[8], fv[8];
#pragma unroll
            for (int w = 0; w < 8; w++) {
                float nm = mv[w] * beta + cv[w] * omb;
                float mt = nm * invn - bb;
                float cnt =
                    (float)((mt > 0.f) + (mt > 1.f) + (mt > 2.f) + (mt > 3.f));
                sv[w] = cnt;
                fv[w] = (cnt > 0.f) ? 0.f : nm;
            }
            *(float4*)(out + idx) = make_float4(sv[0], sv[1], sv[2], sv[3]);
            *(float4*)(out + idx + 4) = make_float4(sv[4], sv[5], sv[6], sv[7]);
            *(float4*)(out + FM_OFF + idx) = make_float4(fv[0], fv[1], fv[2], fv[3]);
            *(float4*)(out + FM_OFF + idx + 4) =
                make_float4(fv[4], fv[5], fv[6], fv[7]);
        }
    }
}

extern "C" void kernel_launch(void* const* d_in, const int* in_sizes, int n_in,
                              void* d_out, int out_size) {
    const float* x    = (const float*)d_in[0];
    const float* mem  = (const float*)d_in[1];
    const float* kern = (const float*)d_in[2];
    const float* beta = (const float*)d_in[3];
    const float* b    = (const float*)d_in[4];
    float* out = (float*)d_out;

    cudaFuncSetAttribute(wino_gemm, cudaFuncAttributeMaxDynamicSharedMemorySize,
                         SMEM_BYTES);

    prep_norm<<<1, 512>>>(kern);
    prep_Wt<<<32, 256>>>(kern);
    prep_Xt<<<1024, 256>>>(x);
    wino_gemm<<<1024, 256, SMEM_BYTES>>>(mem, beta, b, out);
}

// round 9
// speedup vs baseline: 1.4631x; 1.0712x over previous
#include <cuda_runtime.h>
#include <cuda_fp16.h>
#include <cstdint>

#define NB    32
#define CIN   64
#define COUT  128
#define HDIM  64
#define WDIM  64
#define EPSV  1e-8f
#define FM_OFF (NB * COUT * HDIM * WDIM)
#define NTILES 32768              // 32 n * 32 ty * 32 tx (2x2 output tiles)
#define LSC   2048.0f             // lo-plane scale 2^11
#define ILSC  4.8828125e-4f       // 2^-11

// ---- scratch (static __device__, no allocations) ----
__device__ float g_inv_norm[COUT];
// A operand (input transform), fp16 hi + scaled-lo: [pos][tile][ci]
__device__ __align__(128) __half g_Xh[16][NTILES][64];
__device__ __align__(128) __half g_Xl[16][NTILES][64];
// B operand (weight transform): [pos][ci][co]
__device__ __align__(128) __half g_Wh[16][64][128];
__device__ __align__(128) __half g_Wl[16][64][128];

// ---- helpers ----
__device__ __forceinline__ void cpa16(uint32_t dst, const void* src) {
    asm volatile("cp.async.ca.shared.global [%0], [%1], 16;" :: "r"(dst), "l"(src));
}
__device__ __forceinline__ void cpcommit() {
    asm volatile("cp.async.commit_group;" ::: "memory");
}
template <int N>
__device__ __forceinline__ void cpwait() {
    asm volatile("cp.async.wait_group %0;" :: "n"(N) : "memory");
}
__device__ __forceinline__ void ldsm_x4(uint32_t& r0, uint32_t& r1, uint32_t& r2,
                                        uint32_t& r3, uint32_t a) {
    asm volatile("ldmatrix.sync.aligned.m8n8.x4.shared.b16 {%0,%1,%2,%3}, [%4];"
                 : "=r"(r0), "=r"(r1), "=r"(r2), "=r"(r3) : "r"(a));
}
__device__ __forceinline__ void ldsm_x4t(uint32_t& r0, uint32_t& r1, uint32_t& r2,
                                         uint32_t& r3, uint32_t a) {
    asm volatile("ldmatrix.sync.aligned.m8n8.x4.trans.shared.b16 {%0,%1,%2,%3}, [%4];"
                 : "=r"(r0), "=r"(r1), "=r"(r2), "=r"(r3) : "r"(a));
}
__device__ __forceinline__ void mma16(float* d, const uint32_t* a, uint32_t b0,
                                      uint32_t b1) {
    asm volatile(
        "mma.sync.aligned.m16n8k16.row.col.f32.f16.f16.f32 "
        "{%0,%1,%2,%3},{%4,%5,%6,%7},{%8,%9},{%0,%1,%2,%3};"
        : "+f"(d[0]), "+f"(d[1]), "+f"(d[2]), "+f"(d[3])
        : "r"(a[0]), "r"(a[1]), "r"(a[2]), "r"(a[3]), "r"(b0), "r"(b1));
}
__device__ __forceinline__ void hsplit(float v, uint16_t& h, uint16_t& l) {
    __half hb = __float2half(v);
    __half lb = __float2half((v - __half2float(hb)) * LSC);
    h = __half_as_ushort(hb);
    l = __half_as_ushort(lb);
}

// output transform rows A^T = {{1,1,1,0},{0,1,-1,-1}}
__device__ const float cA0[4] = {1.f, 1.f, 1.f, 0.f};
__device__ const float cA1[4] = {0.f, 1.f, -1.f, -1.f};

// ---------- prep: per-Cout 1/(||k||^2 + eps) ----------
__global__ void prep_norm(const float* __restrict__ kern) {
    __shared__ float red[512];
    int t = threadIdx.x;
    int co = t & 127;
    int part = t >> 7;
    float s = 0.f;
#pragma unroll 4
    for (int i = part * 144; i < part * 144 + 144; i++) {
        float v = kern[i * COUT + co];
        s += v * v;
    }
    red[t] = s;
    __syncthreads();
    if (t < 128)
        g_inv_norm[co] = 1.f / (red[co] + red[co + 128] + red[co + 256] + red[co + 384] + EPSV);
}

// ---------- prep: weight transform W~ = G g G^T, fp16 hi/lo ----------
__global__ void prep_Wt(const float* __restrict__ kern) {
    int id = blockIdx.x * 256 + threadIdx.x;   // 8192
    int co = id & 127;
    int ci = id >> 7;

    float g[3][3];
#pragma unroll
    for (int kh = 0; kh < 3; kh++)
#pragma unroll
        for (int kw = 0; kw < 3; kw++)
            g[kh][kw] = kern[(kh * 3 + kw) * (CIN * COUT) + ci * COUT + co];

    float t[4][3];
#pragma unroll
    for (int kw = 0; kw < 3; kw++) {
        t[0][kw] = g[0][kw];
        t[1][kw] = 0.5f * (g[0][kw] + g[1][kw] + g[2][kw]);
        t[2][kw] = 0.5f * (g[0][kw] - g[1][kw] + g[2][kw]);
        t[3][kw] = g[2][kw];
    }
#pragma unroll
    for (int i = 0; i < 4; i++) {
        float wv[4];
        wv[0] = t[i][0];
        wv[1] = 0.5f * (t[i][0] + t[i][1] + t[i][2]);
        wv[2] = 0.5f * (t[i][0] - t[i][1] + t[i][2]);
        wv[3] = t[i][2];
#pragma unroll
        for (int j = 0; j < 4; j++) {
            int p = i * 4 + j;
            uint16_t h, l;
            hsplit(wv[j], h, l);
            g_Wh[p][ci][co] = __ushort_as_half(h);
            g_Wl[p][ci][co] = __ushort_as_half(l);
        }
    }
}

// ---------- prep: input transform X~ = B^T d B, fp16 hi/lo, [pos][tile][ci] ----------
__global__ __launch_bounds__(256)
void prep_Xt(const float* __restrict__ x) {
    const int n = blockIdx.x >> 5;
    const int ty = blockIdx.x & 31;
    const int w = threadIdx.x >> 5;   // warp: 4 tx tiles
    const int l = threadIdx.x & 31;   // ci pair
    const int hb = 2 * ty - 1;

#pragma unroll 1
    for (int t = 0; t < 4; t++) {
        const int tx = w * 4 + t;
        const int tile = n * 1024 + ty * 32 + tx;
        const int wb = 2 * tx - 1;
        uint32_t hv[16], lv[16];

#pragma unroll 1
        for (int cc = 0; cc < 2; cc++) {
            const int ci = 2 * l + cc;
            const float* xp = x + (n * CIN + ci) * (HDIM * WDIM);
            float d[4][4];
#pragma unroll
            for (int r = 0; r < 4; r++) {
                int gr = hb + r;
                bool rok = (gr >= 0) & (gr < HDIM);
#pragma unroll
                for (int c = 0; c < 4; c++) {
                    int gc = wb + c;
                    d[r][c] = (rok & (gc >= 0) & (gc < WDIM)) ? xp[gr * WDIM + gc] : 0.f;
                }
            }
            float s[4][4];
#pragma unroll
            for (int c = 0; c < 4; c++) {
                s[0][c] = d[0][c] - d[2][c];
                s[1][c] = d[1][c] + d[2][c];
                s[2][c] = d[2][c] - d[1][c];
                s[3][c] = d[1][c] - d[3][c];
            }
#pragma unroll
            for (int i = 0; i < 4; i++) {
                float vv[4];
                vv[0] = s[i][0] - s[i][2];
                vv[1] = s[i][1] + s[i][2];
                vv[2] = s[i][2] - s[i][1];
                vv[3] = s[i][1] - s[i][3];
#pragma unroll
                for (int j = 0; j < 4; j++) {
                    int p = i * 4 + j;
                    uint16_t h, lo;
                    hsplit(vv[j], h, lo);
                    if (cc == 0) {
                        hv[p] = (uint32_t)h;
                        lv[p] = (uint32_t)lo;
                    } else {
                        hv[p] |= (uint32_t)h << 16;
                        lv[p] |= (uint32_t)lo << 16;
                    }
                }
            }
        }
#pragma unroll
        for (int p = 0; p < 16; p++) {
            ((uint32_t*)g_Xh[p][tile])[l] = hv[p];
            ((uint32_t*)g_Xl[p][tile])[l] = lv[p];
        }
    }
}

// ---------- main: HMMA fp16x3 Winograd GEMM (16 pos) + fold + fused LIF/spike ----
// smem per buffer (pitch 144B, 64 rows each):
//   A_h +0, A_l +9216, B_h +18432, B_l +27648  (36864 per buffer, x2)
#define BUFB   36864
#define NORMB  73728
#define BIASB  73984
#define SMEM_BYTES 74240
#define PITCH 144

__global__ __launch_bounds__(256, 2)
void wino_gemm(const float* __restrict__ mem, const float* __restrict__ beta_p,
               const float* __restrict__ b_p, float* __restrict__ out) {
    extern __shared__ char smc[];
    float* smf = (float*)smc;
    const uint32_t smu = (uint32_t)__cvta_generic_to_shared(smc);

    const int tid = threadIdx.x;
    const int lane = tid & 31;
    const int wrp = tid >> 5;
    const int mw = wrp & 3;           // M-warp: tiles mw*16..+15
    const int nw = wrp >> 2;          // N-warp: co nw*32..+31
    const int bid = blockIdx.x;
    const int chalf = bid & 1;
    const int TB = (bid >> 1) * 64;   // base tile

    if (tid < 64) {
        smf[NORMB / 4 + tid] = g_inv_norm[chalf * 64 + tid];
        smf[BIASB / 4 + tid] = b_p[chalf * 64 + tid];
    }

#define STAGE(p, buf)                                                         \
    {                                                                         \
        const int pp = (p);                                                   \
        uint32_t base = smu + (buf)*BUFB;                                     \
        _Pragma("unroll")                                                     \
        for (int i = 0; i < 2; i++) {                                         \
            int idx = tid + i * 256;                                          \
            int row = idx >> 3;                                               \
            int c = idx & 7;                                                  \
            cpa16(base + row * PITCH + c * 16, &g_Xh[pp][TB + row][c * 8]);   \
            cpa16(base + 9216 + row * PITCH + c * 16,                         \
                  &g_Xl[pp][TB + row][c * 8]);                                \
            cpa16(base + 18432 + row * PITCH + c * 16,                        \
                  &g_Wh[pp][row][chalf * 64 + c * 8]);                        \
            cpa16(base + 27648 + row * PITCH + c * 16,                        \
                  &g_Wl[pp][row][chalf * 64 + c * 8]);                        \
        }                                                                     \
    }

    float acc[4][16];
#pragma unroll
    for (int q = 0; q < 4; q++)
#pragma unroll
        for (int i = 0; i < 16; i++) acc[q][i] = 0.f;

    // ldmatrix address offsets
    // A (x4, 16x16): lanes 0-15 -> rows mw*16 + (lane&15); lanes 16-31 -> col +8
    const uint32_t arow_off =
        (uint32_t)(mw * 16 + (lane & 15)) * PITCH + (uint32_t)((lane >> 4) * 8) * 2;
    // B (x4 trans, k16 x n16): lanes 0-15 -> k rows (lane&15); lanes 16-31 -> n +8
    const uint32_t brow_off =
        (uint32_t)(lane & 15) * PITCH + (uint32_t)(nw * 32 + (lane >> 4) * 8) * 2;

    STAGE(0, 0);
    cpcommit();

#pragma unroll 1
    for (int p = 0; p < 16; p++) {
        const int buf = p & 1;
        cpwait<0>();
        __syncthreads();
        if (p < 15) {
            STAGE(p + 1, buf ^ 1);
            cpcommit();
        }

        const uint32_t Ab = smu + buf * BUFB;
        float mh[4][4], ml[4][4];
#pragma unroll
        for (int nb = 0; nb < 4; nb++)
#pragma unroll
            for (int k = 0; k < 4; k++) { mh[nb][k] = 0.f; ml[nb][k] = 0.f; }

#pragma unroll
        for (int kb = 0; kb < 4; kb++) {
            uint32_t aAddr = Ab + arow_off + kb * 32;
            uint32_t bAddr = Ab + 18432 + (uint32_t)(kb * 16) * PITCH + brow_off;
            uint32_t ah[4], al[4];
            uint32_t bh0[4], bh1[4], bl0[4], bl1[4];
            ldsm_x4(ah[0], ah[1], ah[2], ah[3], aAddr);
            ldsm_x4(al[0], al[1], al[2], al[3], aAddr + 9216);
            ldsm_x4t(bh0[0], bh0[1], bh0[2], bh0[3], bAddr);          // n 0..15
            ldsm_x4t(bh1[0], bh1[1], bh1[2], bh1[3], bAddr + 32);     // n 16..31
            ldsm_x4t(bl0[0], bl0[1], bl0[2], bl0[3], bAddr + 9216);
            ldsm_x4t(bl1[0], bl1[1], bl1[2], bl1[3], bAddr + 9216 + 32);
            // hi*hi
            mma16(mh[0], ah, bh0[0], bh0[1]);
            mma16(mh[1], ah, bh0[2], bh0[3]);
            mma16(mh[2], ah, bh1[0], bh1[1]);
            mma16(mh[3], ah, bh1[2], bh1[3]);
            // hi*lo
            mma16(ml[0], ah, bl0[0], bl0[1]);
            mma16(ml[1], ah, bl0[2], bl0[3]);
            mma16(ml[2], ah, bl1[0], bl1[1]);
            mma16(ml[3], ah, bl1[2], bl1[3]);
            // lo*hi
            mma16(ml[0], al, bh0[0], bh0[1]);
            mma16(ml[1], al, bh0[2], bh0[3]);
            mma16(ml[2], al, bh1[0], bh1[1]);
            mma16(ml[3], al, bh1[2], bh1[3]);
        }

        // fold: acc[pyx] += AT[py][fi]*AT[px][fj] * (mh + ml*2^-11)
        const int fi = p >> 2, fj = p & 3;
        const float a0i = cA0[fi], a1i = cA1[fi];
        const float a0j = cA0[fj], a1j = cA1[fj];
        float dq[4] = {a0i * a0j, a0i * a1j, a1i * a0j, a1i * a1j};
#pragma unroll
        for (int nb = 0; nb < 4; nb++)
#pragma unroll
            for (int k = 0; k < 4; k++) {
                float mm = fmaf(ml[nb][k], ILSC, mh[nb][k]);
#pragma unroll
                for (int q = 0; q < 4; q++) acc[q][nb * 4 + k] += dq[q] * mm;
            }
    }

    // ---- fused epilogue: LIF membrane + multi-threshold spike ----
    const float beta = *beta_p;
    const float omb = 1.f - beta;

#pragma unroll
    for (int nb = 0; nb < 4; nb++) {
#pragma unroll
        for (int cs = 0; cs < 2; cs++) {
            const int col = nw * 32 + nb * 8 + 2 * (lane & 3) + cs;
            const int co = chalf * 64 + col;
            const float invn = smf[NORMB / 4 + col];
            const float bb = smf[BIASB / 4 + col];
#pragma unroll
            for (int rs = 0; rs < 2; rs++) {
                const int t = TB + mw * 16 + (lane >> 2) + rs * 8;
                const int n = t >> 10;
                const int tyy = (t >> 5) & 31;
                const int txx = t & 31;
                const int mi = nb * 4 + rs * 2 + cs;
                const int base0 = ((n * COUT + co) * HDIM + 2 * tyy) * WDIM + 2 * txx;
#pragma unroll
                for (int py = 0; py < 2; py++) {
                    const int idx = base0 + py * WDIM;
                    float2 mv = *(const float2*)(mem + idx);
                    float c0 = acc[py * 2 + 0][mi];
                    float c1 = acc[py * 2 + 1][mi];
                    float nm0 = mv.x * beta + c0 * omb;
                    float nm1 = mv.y * beta + c1 * omb;
                    float mt0 = nm0 * invn - bb;
                    float mt1 = nm1 * invn - bb;
                    float s0 = (float)((mt0 > 0.f) + (mt0 > 1.f) + (mt0 > 2.f) + (mt0 > 3.f));
                    float s1 = (float)((mt1 > 0.f) + (mt1 > 1.f) + (mt1 > 2.f) + (mt1 > 3.f));
                    float f0 = (s0 > 0.f) ? 0.f : nm0;
                    float f1 = (s1 > 0.f) ? 0.f : nm1;
                    *(float2*)(out + idx) = make_float2(s0, s1);
                    *(float2*)(out + FM_OFF + idx) = make_float2(f0, f1);
                }
            }
        }
    }
}

extern "C" void kernel_launch(void* const* d_in, const int* in_sizes, int n_in,
                              void* d_out, int out_size) {
    const float* x    = (const float*)d_in[0];
    const float* mem  = (const float*)d_in[1];
    const float* kern = (const float*)d_in[2];
    const float* beta = (const float*)d_in[3];
    const float* b    = (const float*)d_in[4];
    float* out = (float*)d_out;

    cudaFuncSetAttribute(wino_gemm, cudaFuncAttributeMaxDynamicSharedMemorySize,
                         SMEM_BYTES);

    prep_norm<<<1, 512>>>(kern);
    prep_Wt<<<32, 256>>>(kern);
    prep_Xt<<<1024, 256>>>(x);
    wino_gemm<<<1024, 256, SMEM_BYTES>>>(mem, beta, b, out);
}

// round 11
// speedup vs baseline: 2.1722x; 1.4846x over previous
#include <cuda_runtime.h>
#include <cuda_fp16.h>
#include <cstdint>

#define NB    32
#define CIN   64
#define COUT  128
#define HDIM  64
#define WDIM  64
#define EPSV  1e-8f
#define FM_OFF (NB * COUT * HDIM * WDIM)
#define NTILES 32768              // 32 n * 32 ty * 32 tx (2x2 output tiles)
#define LSC   2048.0f             // lo-plane scale 2^11
#define ILSC  4.8828125e-4f       // 2^-11

// ---- scratch (static __device__, no allocations) ----
__device__ float g_inv_norm[COUT];
// A operand (input transform), fp16 hi + scaled-lo: [pos][tile][ci]
__device__ __align__(128) __half g_Xh[16][NTILES][64];
__device__ __align__(128) __half g_Xl[16][NTILES][64];
// B operand (weight transform): [pos][ci][co]
__device__ __align__(128) __half g_Wh[16][64][128];
__device__ __align__(128) __half g_Wl[16][64][128];

// ---- helpers ----
__device__ __forceinline__ void cpa16(uint32_t dst, const void* src) {
    asm volatile("cp.async.ca.shared.global [%0], [%1], 16;" :: "r"(dst), "l"(src));
}
__device__ __forceinline__ void cpcommit() {
    asm volatile("cp.async.commit_group;" ::: "memory");
}
template <int N>
__device__ __forceinline__ void cpwait() {
    asm volatile("cp.async.wait_group %0;" :: "n"(N) : "memory");
}
__device__ __forceinline__ void ldsm_x4(uint32_t& r0, uint32_t& r1, uint32_t& r2,
                                        uint32_t& r3, uint32_t a) {
    asm volatile("ldmatrix.sync.aligned.m8n8.x4.shared.b16 {%0,%1,%2,%3}, [%4];"
                 : "=r"(r0), "=r"(r1), "=r"(r2), "=r"(r3) : "r"(a));
}
__device__ __forceinline__ void ldsm_x4t(uint32_t& r0, uint32_t& r1, uint32_t& r2,
                                         uint32_t& r3, uint32_t a) {
    asm volatile("ldmatrix.sync.aligned.m8n8.x4.trans.shared.b16 {%0,%1,%2,%3}, [%4];"
                 : "=r"(r0), "=r"(r1), "=r"(r2), "=r"(r3) : "r"(a));
}
__device__ __forceinline__ void mma16(float* d, const uint32_t* a, uint32_t b0,
                                      uint32_t b1) {
    asm volatile(
        "mma.sync.aligned.m16n8k16.row.col.f32.f16.f16.f32 "
        "{%0,%1,%2,%3},{%4,%5,%6,%7},{%8,%9},{%0,%1,%2,%3};"
        : "+f"(d[0]), "+f"(d[1]), "+f"(d[2]), "+f"(d[3])
        : "r"(a[0]), "r"(a[1]), "r"(a[2]), "r"(a[3]), "r"(b0), "r"(b1));
}
__device__ __forceinline__ void hsplit(float v, uint16_t& h, uint16_t& l) {
    __half hb = __float2half(v);
    __half lb = __float2half((v - __half2float(hb)) * LSC);
    h = __half_as_ushort(hb);
    l = __half_as_ushort(lb);
}

// output transform rows A^T = {{1,1,1,0},{0,1,-1,-1}}
__device__ const float cA0[4] = {1.f, 1.f, 1.f, 0.f};
__device__ const float cA1[4] = {0.f, 1.f, -1.f, -1.f};

// ---------- prep: per-Cout 1/(||k||^2 + eps) ----------
__global__ void prep_norm(const float* __restrict__ kern) {
    __shared__ float red[512];
    int t = threadIdx.x;
    int co = t & 127;
    int part = t >> 7;
    float s = 0.f;
#pragma unroll 4
    for (int i = part * 144; i < part * 144 + 144; i++) {
        float v = kern[i * COUT + co];
        s += v * v;
    }
    red[t] = s;
    __syncthreads();
    if (t < 128)
        g_inv_norm[co] = 1.f / (red[co] + red[co + 128] + red[co + 256] + red[co + 384] + EPSV);
}

// ---------- prep: weight transform W~ = G g G^T, fp16 hi/lo ----------
__global__ void prep_Wt(const float* __restrict__ kern) {
    int id = blockIdx.x * 256 + threadIdx.x;   // 8192
    int co = id & 127;
    int ci = id >> 7;

    float g[3][3];
#pragma unroll
    for (int kh = 0; kh < 3; kh++)
#pragma unroll
        for (int kw = 0; kw < 3; kw++)
            g[kh][kw] = kern[(kh * 3 + kw) * (CIN * COUT) + ci * COUT + co];

    float t[4][3];
#pragma unroll
    for (int kw = 0; kw < 3; kw++) {
        t[0][kw] = g[0][kw];
        t[1][kw] = 0.5f * (g[0][kw] + g[1][kw] + g[2][kw]);
        t[2][kw] = 0.5f * (g[0][kw] - g[1][kw] + g[2][kw]);
        t[3][kw] = g[2][kw];
    }
#pragma unroll
    for (int i = 0; i < 4; i++) {
        float wv[4];
        wv[0] = t[i][0];
        wv[1] = 0.5f * (t[i][0] + t[i][1] + t[i][2]);
        wv[2] = 0.5f * (t[i][0] - t[i][1] + t[i][2]);
        wv[3] = t[i][2];
#pragma unroll
        for (int j = 0; j < 4; j++) {
            int p = i * 4 + j;
            uint16_t h, l;
            hsplit(wv[j], h, l);
            g_Wh[p][ci][co] = __ushort_as_half(h);
            g_Wl[p][ci][co] = __ushort_as_half(l);
        }
    }
}

// ---------- prep: input transform X~ = B^T d B, smem-staged ----------
// Block = (n, ty). Phase 1: coalesced load of 64ci x 4rows x 64cols into dynamic
// smem [r][c][ci] pitch 66 (even -> aligned float2 reads). Phase 2: transforms.
#define XSP 66
#define XT_SMEM (4 * 64 * XSP * 4)
__global__ __launch_bounds__(256)
void prep_Xt(const float* __restrict__ x) {
    extern __shared__ float xs[];
    const int n = blockIdx.x >> 5;
    const int ty = blockIdx.x & 31;
    const int tid = threadIdx.x;
    const int w = tid >> 5;           // warp: 4 tx tiles
    const int l = tid & 31;           // ci pair

    // phase 1: coalesced loads (lane -> column)
#pragma unroll
    for (int i = 0; i < 64; i++) {
        int idx = tid + i * 256;      // 16384 = 64ci * 4r * 64c
        int ci = idx >> 8;
        int rem = idx & 255;
        int r = rem >> 6;
        int c = rem & 63;
        int gr = 2 * ty - 1 + r;
        float v = (gr >= 0 && gr < HDIM)
                      ? __ldg(x + ((n * CIN + ci) * HDIM + gr) * WDIM + c)
                      : 0.f;
        xs[(r * 64 + c) * XSP + ci] = v;
    }
    __syncthreads();

#pragma unroll 1
    for (int t = 0; t < 4; t++) {
        const int tx = w * 4 + t;
        const int tile = n * 1024 + ty * 32 + tx;
        const int wb = 2 * tx - 1;

        // gather 4x4 patch for ci pair (2l, 2l+1) as float2
        float2 d2[4][4];
#pragma unroll
        for (int c = 0; c < 4; c++) {
            int gc = wb + c;
            bool ok = (gc >= 0) & (gc < WDIM);
#pragma unroll
            for (int r = 0; r < 4; r++) {
                d2[r][c] = ok ? *(const float2*)&xs[(r * 64 + gc) * XSP + 2 * l]
                              : make_float2(0.f, 0.f);
            }
        }

        uint32_t hv[16], lv[16];
#pragma unroll
        for (int cc = 0; cc < 2; cc++) {
            float d[4][4];
#pragma unroll
            for (int r = 0; r < 4; r++)
#pragma unroll
                for (int c = 0; c < 4; c++)
                    d[r][c] = cc ? d2[r][c].y : d2[r][c].x;

            float s[4][4];
#pragma unroll
            for (int c = 0; c < 4; c++) {
                s[0][c] = d[0][c] - d[2][c];
                s[1][c] = d[1][c] + d[2][c];
                s[2][c] = d[2][c] - d[1][c];
                s[3][c] = d[1][c] - d[3][c];
            }
#pragma unroll
            for (int i = 0; i < 4; i++) {
                float vv[4];
                vv[0] = s[i][0] - s[i][2];
                vv[1] = s[i][1] + s[i][2];
                vv[2] = s[i][2] - s[i][1];
                vv[3] = s[i][1] - s[i][3];
#pragma unroll
                for (int j = 0; j < 4; j++) {
                    int p = i * 4 + j;
                    uint16_t h, lo;
                    hsplit(vv[j], h, lo);
                    if (cc == 0) {
                        hv[p] = (uint32_t)h;
                        lv[p] = (uint32_t)lo;
                    } else {
                        hv[p] |= (uint32_t)h << 16;
                        lv[p] |= (uint32_t)lo << 16;
                    }
                }
            }
        }
#pragma unroll
        for (int p = 0; p < 16; p++) {
            ((uint32_t*)g_Xh[p][tile])[l] = hv[p];
            ((uint32_t*)g_Xl[p][tile])[l] = lv[p];
        }
    }
}

// ---------- main: HMMA fp16x3 Winograd GEMM (16 pos) + fold + fused LIF/spike ----
// smem per buffer (pitch 144B, 64 rows each):
//   A_h +0, A_l +9216, B_h +18432, B_l +27648  (36864 per buffer, x2)
#define BUFB   36864
#define NORMB  73728
#define BIASB  73984
#define SMEM_BYTES 74240
#define PITCH 144

__global__ __launch_bounds__(256, 2)
void wino_gemm(const float* __restrict__ mem, const float* __restrict__ beta_p,
               const float* __restrict__ b_p, float* __restrict__ out) {
    extern __shared__ char smc[];
    float* smf = (float*)smc;
    const uint32_t smu = (uint32_t)__cvta_generic_to_shared(smc);

    const int tid = threadIdx.x;
    const int lane = tid & 31;
    const int wrp = tid >> 5;
    const int mw = wrp & 3;           // M-warp: tiles mw*16..+15
    const int nw = wrp >> 2;          // N-warp: co nw*32..+31
    const int bid = blockIdx.x;
    const int chalf = bid & 1;
    const int TB = (bid >> 1) * 64;   // base tile

    if (tid < 64) {
        smf[NORMB / 4 + tid] = g_inv_norm[chalf * 64 + tid];
        smf[BIASB / 4 + tid] = b_p[chalf * 64 + tid];
    }

#define STAGE(p, buf)                                                         \
    {                                                                         \
        const int pp = (p);                                                   \
        uint32_t base = smu + (buf)*BUFB;                                     \
        _Pragma("unroll")                                                     \
        for (int i = 0; i < 2; i++) {                                         \
            int idx = tid + i * 256;                                          \
            int row = idx >> 3;                                               \
            int c = idx & 7;                                                  \
            cpa16(base + row * PITCH + c * 16, &g_Xh[pp][TB + row][c * 8]);   \
            cpa16(base + 9216 + row * PITCH + c * 16,                         \
                  &g_Xl[pp][TB + row][c * 8]);                                \
            cpa16(base + 18432 + row * PITCH + c * 16,                        \
                  &g_Wh[pp][row][chalf * 64 + c * 8]);                        \
            cpa16(base + 27648 + row * PITCH + c * 16,                        \
                  &g_Wl[pp][row][chalf * 64 + c * 8]);                        \
        }                                                                     \
    }

    float acc[4][16];
#pragma unroll
    for (int q = 0; q < 4; q++)
#pragma unroll
        for (int i = 0; i < 16; i++) acc[q][i] = 0.f;

    // ldmatrix address offsets
    const uint32_t arow_off =
        (uint32_t)(mw * 16 + (lane & 15)) * PITCH + (uint32_t)((lane >> 4) * 8) * 2;
    const uint32_t brow_off =
        (uint32_t)(lane & 15) * PITCH + (uint32_t)(nw * 32 + (lane >> 4) * 8) * 2;

    STAGE(0, 0);
    cpcommit();

#pragma unroll 1
    for (int p = 0; p < 16; p++) {
        const int buf = p & 1;
        cpwait<0>();
        __syncthreads();
        if (p < 15) {
            STAGE(p + 1, buf ^ 1);
            cpcommit();
        }

        const uint32_t Ab = smu + buf * BUFB;
        float mh[4][4], ml[4][4];
#pragma unroll
        for (int nb = 0; nb < 4; nb++)
#pragma unroll
            for (int k = 0; k < 4; k++) { mh[nb][k] = 0.f; ml[nb][k] = 0.f; }

#pragma unroll
        for (int kb = 0; kb < 4; kb++) {
            uint32_t aAddr = Ab + arow_off + kb * 32;
            uint32_t bAddr = Ab + 18432 + (uint32_t)(kb * 16) * PITCH + brow_off;
            uint32_t ah[4], al[4];
            uint32_t bh0[4], bh1[4], bl0[4], bl1[4];
            ldsm_x4(ah[0], ah[1], ah[2], ah[3], aAddr);
            ldsm_x4(al[0], al[1], al[2], al[3], aAddr + 9216);
            ldsm_x4t(bh0[0], bh0[1], bh0[2], bh0[3], bAddr);          // n 0..15
            ldsm_x4t(bh1[0], bh1[1], bh1[2], bh1[3], bAddr + 32);     // n 16..31
            ldsm_x4t(bl0[0], bl0[1], bl0[2], bl0[3], bAddr + 9216);
            ldsm_x4t(bl1[0], bl1[1], bl1[2], bl1[3], bAddr + 9216 + 32);
            // hi*hi
            mma16(mh[0], ah, bh0[0], bh0[1]);
            mma16(mh[1], ah, bh0[2], bh0[3]);
            mma16(mh[2], ah, bh1[0], bh1[1]);
            mma16(mh[3], ah, bh1[2], bh1[3]);
            // hi*lo
            mma16(ml[0], ah, bl0[0], bl0[1]);
            mma16(ml[1], ah, bl0[2], bl0[3]);
            mma16(ml[2], ah, bl1[0], bl1[1]);
            mma16(ml[3], ah, bl1[2], bl1[3]);
            // lo*hi
            mma16(ml[0], al, bh0[0], bh0[1]);
            mma16(ml[1], al, bh0[2], bh0[3]);
            mma16(ml[2], al, bh1[0], bh1[1]);
            mma16(ml[3], al, bh1[2], bh1[3]);
        }

        // fold: acc[pyx] += AT[py][fi]*AT[px][fj] * (mh + ml*2^-11)
        const int fi = p >> 2, fj = p & 3;
        const float a0i = cA0[fi], a1i = cA1[fi];
        const float a0j = cA0[fj], a1j = cA1[fj];
        float dq[4] = {a0i * a0j, a0i * a1j, a1i * a0j, a1i * a1j};
#pragma unroll
        for (int nb = 0; nb < 4; nb++)
#pragma unroll
            for (int k = 0; k < 4; k++) {
                float mm = fmaf(ml[nb][k], ILSC, mh[nb][k]);
#pragma unroll
                for (int q = 0; q < 4; q++) acc[q][nb * 4 + k] += dq[q] * mm;
            }
    }

    // ---- fused epilogue: LIF membrane + multi-threshold spike ----
    const float beta = *beta_p;
    const float omb = 1.f - beta;

#pragma unroll
    for (int nb = 0; nb < 4; nb++) {
#pragma unroll
        for (int cs = 0; cs < 2; cs++) {
            const int col = nw * 32 + nb * 8 + 2 * (lane & 3) + cs;
            const int co = chalf * 64 + col;
            const float invn = smf[NORMB / 4 + col];
            const float bb = smf[BIASB / 4 + col];
#pragma unroll
            for (int rs = 0; rs < 2; rs++) {
                const int t = TB + mw * 16 + (lane >> 2) + rs * 8;
                const int n = t >> 10;
                const int tyy = (t >> 5) & 31;
                const int txx = t & 31;
                const int mi = nb * 4 + rs * 2 + cs;
                const int base0 = ((n * COUT + co) * HDIM + 2 * tyy) * WDIM + 2 * txx;
#pragma unroll
                for (int py = 0; py < 2; py++) {
                    const int idx = base0 + py * WDIM;
                    float2 mv = *(const float2*)(mem + idx);
                    float c0 = acc[py * 2 + 0][mi];
                    float c1 = acc[py * 2 + 1][mi];
                    float nm0 = mv.x * beta + c0 * omb;
                    float nm1 = mv.y * beta + c1 * omb;
                    float mt0 = nm0 * invn - bb;
                    float mt1 = nm1 * invn - bb;
                    float s0 = (float)((mt0 > 0.f) + (mt0 > 1.f) + (mt0 > 2.f) + (mt0 > 3.f));
                    float s1 = (float)((mt1 > 0.f) + (mt1 > 1.f) + (mt1 > 2.f) + (mt1 > 3.f));
                    float f0 = (s0 > 0.f) ? 0.f : nm0;
                    float f1 = (s1 > 0.f) ? 0.f : nm1;
                    *(float2*)(out + idx) = make_float2(s0, s1);
                    *(float2*)(out + FM_OFF + idx) = make_float2(f0, f1);
                }
            }
        }
    }
}

extern "C" void kernel_launch(void* const* d_in, const int* in_sizes, int n_in,
                              void* d_out, int out_size) {
    const float* x    = (const float*)d_in[0];
    const float* mem  = (const float*)d_in[1];
    const float* kern = (const float*)d_in[2];
    const float* beta = (const float*)d_in[3];
    const float* b    = (const float*)d_in[4];
    float* out = (float*)d_out;

    cudaFuncSetAttribute(wino_gemm, cudaFuncAttributeMaxDynamicSharedMemorySize,
                         SMEM_BYTES);
    cudaFuncSetAttribute(prep_Xt, cudaFuncAttributeMaxDynamicSharedMemorySize,
                         XT_SMEM);

    prep_norm<<<1, 512>>>(kern);
    prep_Wt<<<32, 256>>>(kern);
    prep_Xt<<<1024, 256, XT_SMEM>>>(x);
    wino_gemm<<<1024, 256, SMEM_BYTES>>>(mem, beta, b, out);
}